// round 16
// baseline (speedup 1.0000x reference)
#include <cuda_runtime.h>
#include <cuda_fp16.h>
#include <cstdint>

// Block-sparse batched linear, single fused persistent kernel (sm_103-safe):
//   Y[i] = sum_{k: i_idx[k]==i} ( X[j_idx[k]] @ W[k] + b[k] )
// Round 16: X->fp16 conversion OVERLAPPED with the GEMM. Head-converts only
// m-groups 0..12 (~5us); thereafter the CTA processing tile t also converts
// share (t+296)%24 of m-group (t+296)/24 (1 float4/thread/chunk, LDG before
// the MMA burst, STG after). Per-group release counters gate consumers
// (acquire spin, groups >=13 only). GEMM core = round 8/12 proven best:
// CTA 128x128, 4 warps (64x64 tiles), fp16 mma.sync.m16n8k16 w/ f32 accum,
// 4-stage per-tile cp.async pipeline, persistent 296 CTAs (2/SM).

namespace {

constexpr int NBLK   = 12;
constexpr int DDIM   = 256;
constexpr int BATCHN = 8192;
constexpr int NACT   = 48;

constexpr int BM = 128;
constexpr int BN = 128;
constexpr int BK = 32;
constexpr int NCH = 32;          // 4 active blocks * 8 k-chunks per tile
constexpr int NSTG = 4;
constexpr int THREADS = 128;
constexpr int GRIDP  = 296;      // 2 CTAs/SM; co-resident on 148/152-SM parts
constexpr int NT     = NBLK * (DDIM / BN) * (BATCHN / BM);   // 1536 tiles
constexpr int NGRP   = 64;       // m-groups (BATCHN/BM)
constexpr int HEADG  = 13;       // groups converted up front

constexpr uint32_t ROWB  = 80;            // 64B data + 16B pad per 32-elem row
constexpr uint32_t ASZ   = 128 * ROWB;    // 10240 B per operand tile
constexpr uint32_t OFF_A = 0;
constexpr uint32_t OFF_B = ASZ;
constexpr uint32_t STAGE_BYTES = 2 * ASZ;                  // 20480
constexpr uint32_t SM_BIAS     = NSTG * STAGE_BYTES;       // 81920
constexpr uint32_t SMEM_TOTAL  = SM_BIAS + 128 * 4;        // 82432

// ---- device scratch (static; no runtime allocation) ----
__device__ __half g_Xf[(size_t)NBLK * BATCHN * DDIM];
__device__ __half g_Wtf[(size_t)NACT * DDIM * DDIM];   // [blk][n][k]
__device__ unsigned int g_bar;          // monotonic ticket barrier
__device__ unsigned int g_cnt[NGRP];    // per-group conversion counters

// ---------------- helpers ----------------
__device__ __forceinline__ uint32_t smem_u32(const void* p) {
    uint32_t a;
    asm("{ .reg .u64 t; cvta.to.shared.u64 t, %1; cvt.u32.u64 %0, t; }"
        : "=r"(a) : "l"(p));
    return a;
}
__device__ __forceinline__ void cp16(uint32_t dst, const void* src) {
    asm volatile("cp.async.cg.shared.global [%0], [%1], 16;\n" :: "r"(dst), "l"(src));
}
__device__ __forceinline__ void cp_commit() { asm volatile("cp.async.commit_group;\n"); }
template <int N>
__device__ __forceinline__ void cp_wait() { asm volatile("cp.async.wait_group %0;\n" :: "n"(N)); }

__device__ __forceinline__ void ldsm4(uint32_t r[4], uint32_t addr) {
    asm volatile("ldmatrix.sync.aligned.m8n8.x4.shared.b16 {%0,%1,%2,%3}, [%4];"
                 : "=r"(r[0]), "=r"(r[1]), "=r"(r[2]), "=r"(r[3]) : "r"(addr));
}
__device__ __forceinline__ void mma_f16(float d[4], const uint32_t a[4],
                                        uint32_t b0, uint32_t b1) {
    asm volatile(
        "mma.sync.aligned.m16n8k16.row.col.f32.f16.f16.f32 "
        "{%0,%1,%2,%3}, {%4,%5,%6,%7}, {%8,%9}, {%0,%1,%2,%3};\n"
        : "+f"(d[0]), "+f"(d[1]), "+f"(d[2]), "+f"(d[3])
        : "r"(a[0]), "r"(a[1]), "r"(a[2]), "r"(a[3]), "r"(b0), "r"(b1));
}
__device__ __forceinline__ uint2 cvt4(float4 v) {
    __half2 p0 = __floats2half2_rn(v.x, v.y);
    __half2 p1 = __floats2half2_rn(v.z, v.w);
    return make_uint2(*reinterpret_cast<uint32_t*>(&p0),
                      *reinterpret_cast<uint32_t*>(&p1));
}
__device__ __forceinline__ uint32_t ld_acq(const unsigned int* p) {
    uint32_t v;
    asm volatile("ld.acquire.gpu.global.u32 %0, [%1];" : "=r"(v) : "l"(p) : "memory");
    return v;
}
__device__ __forceinline__ void red_rel_add1(unsigned int* p) {
    asm volatile("red.release.gpu.global.add.u32 [%0], %1;" :: "l"(p), "r"(1u)
                 : "memory");
}

struct Tile {
    int m0, n0, ib;
    int kact[4], jact[4];
};

__device__ __forceinline__ void decode_tile(int t, const int* i_idx,
                                            const int* j_idx, Tile& tl) {
    const int ibnh = t % 24;          // (ib, n-half) fastest -> L2 sharing
    tl.ib = ibnh >> 1;
    tl.n0 = (ibnh & 1) * BN;
    tl.m0 = (t / 24) * BM;
    int na = 0;
    #pragma unroll 1
    for (int k = 0; k < NACT; ++k) {
        if (__ldg(i_idx + k) == tl.ib) {
            if (na < 4) { tl.kact[na] = k; tl.jact[na] = __ldg(j_idx + k); }
            ++na;
        }
    }
}

__device__ __forceinline__ void chunk_srcs(const Tile& tl, int c,
                                           const __half*& A, const __half*& B) {
    const int a  = c >> 3;
    const int kk = (c & 7) * BK;
    A = g_Xf  + ((size_t)tl.jact[a] * BATCHN + tl.m0) * DDIM + kk;
    B = g_Wtf + ((size_t)tl.kact[a] * DDIM + tl.n0) * DDIM + kk;
}

__device__ __forceinline__ void load_chunk(
    uint32_t stage_base, int tid, const __half* A, const __half* B)
{
    #pragma unroll
    for (int t = 0; t < 4; ++t) {
        const int slot = tid + t * THREADS;       // 0..511
        const int row  = slot >> 2;               // 0..127
        const int c16  = slot & 3;
        const uint32_t dst = (uint32_t)row * ROWB + (uint32_t)c16 * 16;
        const size_t   so  = (size_t)row * DDIM + c16 * 8;
        cp16(stage_base + OFF_A + dst, A + so);
        cp16(stage_base + OFF_B + dst, B + so);
    }
}

// ---------------- the single fused kernel ----------------
__global__ void __launch_bounds__(THREADS, 2)
bs_fused_kernel(const float* __restrict__ X,
                const float* __restrict__ W,
                const float* __restrict__ Bv,
                const int*   __restrict__ i_idx,
                const int*   __restrict__ j_idx,
                float*       __restrict__ Y)
{
    extern __shared__ __align__(128) char smem[];
    const uint32_t sb = smem_u32(smem);
    const int tid = threadIdx.x;

    // ===== phase 1a: reset group counters (pre-barrier => replay-safe) =====
    if (blockIdx.x < NGRP && tid == 0) g_cnt[blockIdx.x] = 0u;

    // ===== phase 1b: W -> transposed [n][k] fp16 (smem tiles) =====
    {
        float* ts = reinterpret_cast<float*>(smem);       // 32x33 f32 tile
        const int ty = tid >> 5, tx = tid & 31;           // ty 0..3
        #pragma unroll 1
        for (int s = blockIdx.x; s < NACT * 64; s += GRIDP) {
            const int blk = s >> 6, r = s & 63;
            const int k0 = (r >> 3) * 32, n0 = (r & 7) * 32;
            __syncthreads();
            #pragma unroll
            for (int j = 0; j < 8; ++j) {
                const int y = ty + j * 4;
                ts[y * 33 + tx] =
                    W[((size_t)blk * DDIM + k0 + y) * DDIM + n0 + tx];
            }
            __syncthreads();
            #pragma unroll
            for (int j = 0; j < 8; ++j) {
                const int y = ty + j * 4;
                g_Wtf[((size_t)blk * DDIM + n0 + y) * DDIM + k0 + tx] =
                    __float2half_rn(ts[tx * 33 + y]);
            }
        }
    }

    // ===== phase 1c: head X conversion (m-groups 0..HEADG-1) =====
    {
        const int HM = HEADG * BM;                       // 1664 head rows
        const size_t head4 = (size_t)NBLK * HM * 64;     // float4 count
        const size_t nth = (size_t)GRIDP * THREADS;
        for (size_t i = (size_t)blockIdx.x * THREADS + tid; i < head4; i += nth) {
            const int j  = (int)(i / ((size_t)HM * 64));
            const int r  = (int)((i / 64) % HM);
            const int c4 = (int)(i & 63);
            const size_t f4 = ((size_t)j * BATCHN + r) * 64 + c4;
            reinterpret_cast<uint2*>(g_Xf)[f4] =
                cvt4(reinterpret_cast<const float4*>(X)[f4]);
        }
    }

    // ================= global software barrier =================
    __threadfence();
    __syncthreads();
    if (tid == 0) {
        const unsigned ticket = atomicAdd(&g_bar, 1u);
        const unsigned target = (ticket / GRIDP + 1u) * GRIDP;
        unsigned v;
        do {
            asm volatile("ld.volatile.global.u32 %0, [%1];"
                         : "=r"(v) : "l"(&g_bar));
        } while (v < target);
    }
    __syncthreads();
    __threadfence();

    // ================= phase 2: persistent GEMM + overlapped conversion ====
    const int wid    = tid >> 5;
    const int lane   = tid & 31;
    const int g      = lane >> 2;
    const int tg     = lane & 3;
    const int warp_m = wid >> 1;     // 0..1  (64 rows)
    const int warp_n = wid & 1;      // 0..1  (64 cols)
    const int lrow   = lane & 15;
    const int lseg   = lane >> 4;

    #pragma unroll 1
    for (int t = blockIdx.x; t < NT; t += GRIDP) {
        Tile cur;
        decode_tile(t, i_idx, j_idx, cur);

        // gate: this tile's m-group must be fully converted
        const int G = t / 24;
        if (G >= HEADG) {
            if (tid == 0)
                while (ld_acq(&g_cnt[G]) < 24u) { }
            __syncthreads();
        }

        // production task: share (t+296)%24 of group (t+296)/24
        const int  s    = t + GRIDP;
        const bool prod = (t >= 16) && (s < NT);
        const int  Gp   = s / 24;
        const uint32_t qb = (uint32_t)(s % 24) * 4096u;  // float4 base in group

        // prologue: chunks 0..2
        #pragma unroll
        for (int c = 0; c < NSTG - 1; ++c) {
            const __half *A, *B;
            chunk_srcs(cur, c, A, B);
            load_chunk(sb + (uint32_t)c * STAGE_BYTES, tid, A, B);
            cp_commit();
        }

        float acc[4][8][4];
        #pragma unroll
        for (int mt = 0; mt < 4; ++mt)
            #pragma unroll
            for (int nt = 0; nt < 8; ++nt)
                #pragma unroll
                for (int q = 0; q < 4; ++q)
                    acc[mt][nt][q] = 0.0f;

        for (int c = 0; c < NCH; ++c) {
            cp_wait<NSTG - 2>();      // chunk c resident
            __syncthreads();          // protects stage (c+3)%4 reuse

            if (c + NSTG - 1 < NCH) {
                const __half *A, *B;
                chunk_srcs(cur, c + NSTG - 1, A, B);
                load_chunk(sb + (uint32_t)((c + NSTG - 1) % NSTG) * STAGE_BYTES,
                           tid, A, B);
            }
            cp_commit();              // keeps group accounting aligned

            // conversion LDG issued early; latency hidden by the MMA burst
            float4 pv;
            size_t pf4 = 0;
            if (prod) {
                const uint32_t q  = qb + (uint32_t)c * 128u + (uint32_t)tid;
                const int j  = (int)(q >> 13);
                const int r  = (int)((q >> 6) & 127u);
                const int c4 = (int)(q & 63u);
                pf4 = ((size_t)j * BATCHN + (size_t)Gp * BM + r) * 64 + c4;
                pv  = reinterpret_cast<const float4*>(X)[pf4];
            }

            const uint32_t st = sb + (uint32_t)(c % NSTG) * STAGE_BYTES;
            const uint32_t aB = st + OFF_A, bB = st + OFF_B;

            #pragma unroll
            for (int h = 0; h < 2; ++h) {
                const uint32_t fcol = (uint32_t)(h * 32 + lseg * 16);
                const uint32_t bo = (uint32_t)(warp_n * 64 + lrow) * ROWB + fcol;
                uint32_t b[4][4];
                ldsm4(b[0], bB + bo);
                ldsm4(b[1], bB + bo + 16 * ROWB);
                ldsm4(b[2], bB + bo + 32 * ROWB);
                ldsm4(b[3], bB + bo + 48 * ROWB);

                #pragma unroll
                for (int mt = 0; mt < 4; ++mt) {
                    const uint32_t ao =
                        (uint32_t)(warp_m * 64 + mt * 16 + lrow) * ROWB + fcol;
                    uint32_t a[4];
                    ldsm4(a, aB + ao);
                    #pragma unroll
                    for (int tt = 0; tt < 4; ++tt) {
                        mma_f16(acc[mt][tt * 2 + 0], a, b[tt][0], b[tt][2]);
                        mma_f16(acc[mt][tt * 2 + 1], a, b[tt][1], b[tt][3]);
                    }
                }
            }

            if (prod)   // consume LDG result after the burst
                reinterpret_cast<uint2*>(g_Xf)[pf4] = cvt4(pv);
        }

        // ---- epilogue
        __syncthreads();
        if (tid < BN) {
            const int col = cur.n0 + tid;
            float bs = __ldg(Bv + (size_t)cur.kact[0] * DDIM + col)
                     + __ldg(Bv + (size_t)cur.kact[1] * DDIM + col)
                     + __ldg(Bv + (size_t)cur.kact[2] * DDIM + col)
                     + __ldg(Bv + (size_t)cur.kact[3] * DDIM + col);
            reinterpret_cast<float*>(smem + SM_BIAS)[tid] = bs;
        }
        __syncthreads();
        const float* biasp = reinterpret_cast<const float*>(smem + SM_BIAS);

        #pragma unroll
        for (int mt = 0; mt < 4; ++mt) {
            const int row = cur.m0 + warp_m * 64 + mt * 16 + g;
            #pragma unroll
            for (int nt = 0; nt < 8; ++nt) {
                const int lc  = warp_n * 64 + nt * 8 + tg * 2;
                const float b0 = biasp[lc], b1 = biasp[lc + 1];
                const size_t o0 =
                    ((size_t)cur.ib * BATCHN + row) * DDIM + cur.n0 + lc;
                const size_t o1 = o0 + (size_t)8 * DDIM;
                *reinterpret_cast<float2*>(Y + o0) =
                    make_float2(acc[mt][nt][0] + b0, acc[mt][nt][1] + b1);
                *reinterpret_cast<float2*>(Y + o1) =
                    make_float2(acc[mt][nt][2] + b0, acc[mt][nt][3] + b1);
            }
        }

        // publish this tile's conversion share (all STGs fenced first)
        if (prod) {
            __threadfence();
            __syncthreads();
            if (tid == 0) red_rel_add1(&g_cnt[Gp]);
        }
        __syncthreads();   // bias smem reuse guard for next tile
    }
}

} // namespace

extern "C" void kernel_launch(void* const* d_in, const int* in_sizes, int n_in,
                              void* d_out, int out_size) {
    const float* X     = (const float*)d_in[0];
    const float* W     = (const float*)d_in[1];
    const float* b     = (const float*)d_in[2];
    const int*   i_idx = (const int*)d_in[3];
    const int*   j_idx = (const int*)d_in[4];
    float*       Y     = (float*)d_out;

    cudaFuncSetAttribute(bs_fused_kernel,
                         cudaFuncAttributeMaxDynamicSharedMemorySize, SMEM_TOTAL);

    bs_fused_kernel<<<GRIDP, THREADS, SMEM_TOTAL>>>(X, W, b, i_idx, j_idx, Y);
}

// round 17
// speedup vs baseline: 1.1364x; 1.1364x over previous
#include <cuda_runtime.h>
#include <cuda_fp16.h>
#include <cstdint>

// Block-sparse batched linear (sm_103 family-safe: mma.sync + ldmatrix):
//   Y[i] = sum_{k: i_idx[k]==i} ( X[j_idx[k]] @ W[k] + b[k] )
// Round 17 = round-8 champion GEMM + single merged prep launch.
// Prep (one kernel): blocks [0,24576) convert X -> fp16; blocks >= 24576
// transpose+convert W -> [n][k] fp16 via smem tiles.
// Main: CTA 128x128, 4 warps (2x2 grid, 64x64 warp tiles), single-pass fp16
// mma.sync.m16n8k16 w/ f32 accum, ldmatrix.x4 feeds, 4-stage cp.async
// pipeline (BK=32, wait<2>), 2 CTAs/SM.

namespace {

constexpr int NBLK   = 12;
constexpr int DDIM   = 256;
constexpr int BATCHN = 8192;
constexpr int NACT   = 48;

constexpr int BM = 128;
constexpr int BN = 128;
constexpr int BK = 32;
constexpr int NCH = 32;          // 4 active blocks * 8 k-chunks
constexpr int NSTG = 4;
constexpr int THREADS = 128;

constexpr uint32_t ROWB  = 80;            // 64B data + 16B pad per 32-elem row
constexpr uint32_t ASZ   = 128 * ROWB;    // 10240 B per operand tile
constexpr uint32_t OFF_A = 0;
constexpr uint32_t OFF_B = ASZ;
constexpr uint32_t STAGE_BYTES = 2 * ASZ;                  // 20480
constexpr uint32_t SM_BIAS     = NSTG * STAGE_BYTES;       // 81920
constexpr uint32_t SMEM_TOTAL  = SM_BIAS + 128 * 4;        // 82432

// prep kernel partitioning
constexpr int XCONV_BLOCKS = NBLK * BATCHN * DDIM / 4 / 256;   // 24576
constexpr int WCONV_BLOCKS = NACT * 64;                        // 3072
constexpr int PREP_BLOCKS  = XCONV_BLOCKS + WCONV_BLOCKS;      // 27648

// ---- device scratch (static; no runtime allocation) ----
__device__ __half g_Xf[(size_t)NBLK * BATCHN * DDIM];
__device__ __half g_Wtf[(size_t)NACT * DDIM * DDIM];   // [blk][n][k]

// ---------------- helpers ----------------
__device__ __forceinline__ uint32_t smem_u32(const void* p) {
    uint32_t a;
    asm("{ .reg .u64 t; cvta.to.shared.u64 t, %1; cvt.u32.u64 %0, t; }"
        : "=r"(a) : "l"(p));
    return a;
}
__device__ __forceinline__ void cp16(uint32_t dst, const void* src) {
    asm volatile("cp.async.cg.shared.global [%0], [%1], 16;\n" :: "r"(dst), "l"(src));
}
__device__ __forceinline__ void cp_commit() { asm volatile("cp.async.commit_group;\n"); }
template <int N>
__device__ __forceinline__ void cp_wait() { asm volatile("cp.async.wait_group %0;\n" :: "n"(N)); }

__device__ __forceinline__ void ldsm4(uint32_t r[4], uint32_t addr) {
    asm volatile("ldmatrix.sync.aligned.m8n8.x4.shared.b16 {%0,%1,%2,%3}, [%4];"
                 : "=r"(r[0]), "=r"(r[1]), "=r"(r[2]), "=r"(r[3]) : "r"(addr));
}
__device__ __forceinline__ void mma_f16(float d[4], const uint32_t a[4],
                                        uint32_t b0, uint32_t b1) {
    asm volatile(
        "mma.sync.aligned.m16n8k16.row.col.f32.f16.f16.f32 "
        "{%0,%1,%2,%3}, {%4,%5,%6,%7}, {%8,%9}, {%0,%1,%2,%3};\n"
        : "+f"(d[0]), "+f"(d[1]), "+f"(d[2]), "+f"(d[3])
        : "r"(a[0]), "r"(a[1]), "r"(a[2]), "r"(a[3]), "r"(b0), "r"(b1));
}

// ---------------- merged prep kernel ----------------
__global__ void __launch_bounds__(256) prep_kernel(const float* __restrict__ X,
                                                   const float* __restrict__ W) {
    if (blockIdx.x < XCONV_BLOCKS) {
        // ---- X -> fp16, one float4 per thread
        const size_t i = (size_t)blockIdx.x * 256 + threadIdx.x;
        const float4 v = reinterpret_cast<const float4*>(X)[i];
        __half2 p0 = __floats2half2_rn(v.x, v.y);
        __half2 p1 = __floats2half2_rn(v.z, v.w);
        reinterpret_cast<uint2*>(g_Xf)[i] = make_uint2(
            *reinterpret_cast<uint32_t*>(&p0), *reinterpret_cast<uint32_t*>(&p1));
    } else {
        // ---- W 32x32 subtile transpose + convert
        __shared__ float ts[32][33];
        const int s   = blockIdx.x - XCONV_BLOCKS;   // 0..3071
        const int blk = s >> 6;
        const int r   = s & 63;
        const int k0  = (r >> 3) * 32;
        const int n0  = (r & 7) * 32;
        const int tx  = threadIdx.x & 31;
        const int ty  = threadIdx.x >> 5;            // 0..7
        #pragma unroll
        for (int j = 0; j < 4; ++j) {
            const int y = ty + j * 8;
            ts[y][tx] = W[((size_t)blk * DDIM + k0 + y) * DDIM + n0 + tx];
        }
        __syncthreads();
        #pragma unroll
        for (int j = 0; j < 4; ++j) {
            const int y = ty + j * 8;   // n-offset
            g_Wtf[((size_t)blk * DDIM + n0 + y) * DDIM + k0 + tx] =
                __float2half_rn(ts[tx][y]);
        }
    }
}

// ---------------- main kernel (round-8 champion, verbatim) ----------------
__device__ __forceinline__ void load_chunk(
    uint32_t stage_base, int tid, const __half* A, const __half* B)
{
    #pragma unroll
    for (int t = 0; t < 4; ++t) {
        const int slot = tid + t * THREADS;       // 0..511
        const int row  = slot >> 2;               // 0..127
        const int c16  = slot & 3;                // 16B chunk within 64B row
        const uint32_t dst = (uint32_t)row * ROWB + (uint32_t)c16 * 16;
        const size_t   so  = (size_t)row * DDIM + c16 * 8;
        cp16(stage_base + OFF_A + dst, A + so);
        cp16(stage_base + OFF_B + dst, B + so);
    }
}

__global__ void __launch_bounds__(THREADS, 2)
bs_mma_kernel(const float* __restrict__ Bv,
              const int*   __restrict__ i_idx,
              const int*   __restrict__ j_idx,
              float*       __restrict__ Y)
{
    extern __shared__ __align__(128) char smem[];
    const uint32_t sb = smem_u32(smem);

    const int tid    = threadIdx.x;
    const int wid    = tid >> 5;
    const int lane   = tid & 31;
    const int g      = lane >> 2;
    const int tg     = lane & 3;
    const int warp_m = wid >> 1;     // 0..1  (64 rows)
    const int warp_n = wid & 1;      // 0..1  (64 cols)
    const int lrow   = lane & 15;
    const int lseg   = lane >> 4;

    const int m0 = blockIdx.x * BM;
    const int n0 = blockIdx.y * BN;
    const int ib = blockIdx.z;

    // active blocks feeding output row ib (exactly 4 by pattern construction)
    int kact[4], jact[4];
    {
        int na = 0;
        #pragma unroll 1
        for (int k = 0; k < NACT; ++k) {
            if (__ldg(i_idx + k) == ib) {
                if (na < 4) { kact[na] = k; jact[na] = __ldg(j_idx + k); }
                ++na;
            }
        }
    }

    // 64x64 warp tile: acc[mt 0..3][nt 0..7][4]
    float acc[4][8][4];
    #pragma unroll
    for (int mt = 0; mt < 4; ++mt)
        #pragma unroll
        for (int nt = 0; nt < 8; ++nt)
            #pragma unroll
            for (int q = 0; q < 4; ++q)
                acc[mt][nt][q] = 0.0f;

    auto chunk_srcs = [&](int c, const __half*& A, const __half*& B) {
        const int a  = c >> 3;
        const int kk = (c & 7) * BK;
        A = g_Xf  + ((size_t)jact[a] * BATCHN + m0) * DDIM + kk;
        B = g_Wtf + ((size_t)kact[a] * DDIM + n0) * DDIM + kk;
    };

    // prologue: preload NSTG-1 = 3 chunks
    #pragma unroll
    for (int c = 0; c < NSTG - 1; ++c) {
        const __half *A, *B;
        chunk_srcs(c, A, B);
        load_chunk(sb + (uint32_t)c * STAGE_BYTES, tid, A, B);
        cp_commit();
    }

    for (int c = 0; c < NCH; ++c) {
        cp_wait<NSTG - 2>();          // chunk c resident
        __syncthreads();              // protects reuse of stage (c-1)%NSTG

        if (c + NSTG - 1 < NCH) {
            const __half *A, *B;
            chunk_srcs(c + NSTG - 1, A, B);
            load_chunk(sb + (uint32_t)((c + NSTG - 1) % NSTG) * STAGE_BYTES, tid, A, B);
            cp_commit();
        } else {
            cp_commit();              // keep group accounting aligned
        }

        const uint32_t st = sb + (uint32_t)(c % NSTG) * STAGE_BYTES;
        const uint32_t aB = st + OFF_A, bB = st + OFF_B;

        #pragma unroll
        for (int ks = 0; ks < BK; ks += 16) {
            const uint32_t fcol = (uint32_t)(ks * 2 + lseg * 16);
            // B fragments: 4 x ldsm.x4 covering 64 n-cols
            const uint32_t bo = (uint32_t)(warp_n * 64 + lrow) * ROWB + fcol;
            uint32_t b[4][4];
            ldsm4(b[0], bB + bo);
            ldsm4(b[1], bB + bo + 16 * ROWB);
            ldsm4(b[2], bB + bo + 32 * ROWB);
            ldsm4(b[3], bB + bo + 48 * ROWB);

            #pragma unroll
            for (int mt = 0; mt < 4; ++mt) {
                const uint32_t ao =
                    (uint32_t)(warp_m * 64 + mt * 16 + lrow) * ROWB + fcol;
                uint32_t a[4];
                ldsm4(a, aB + ao);
                #pragma unroll
                for (int t = 0; t < 4; ++t) {
                    mma_f16(acc[mt][t * 2 + 0], a, b[t][0], b[t][2]);
                    mma_f16(acc[mt][t * 2 + 1], a, b[t][1], b[t][3]);
                }
            }
        }
    }

    // bias sums for this CTA's 128 output cols
    __syncthreads();
    if (tid < BN) {
        const int col = n0 + tid;
        float bs = __ldg(Bv + (size_t)kact[0] * DDIM + col)
                 + __ldg(Bv + (size_t)kact[1] * DDIM + col)
                 + __ldg(Bv + (size_t)kact[2] * DDIM + col)
                 + __ldg(Bv + (size_t)kact[3] * DDIM + col);
        reinterpret_cast<float*>(smem + SM_BIAS)[tid] = bs;
    }
    __syncthreads();
    const float* biasp = reinterpret_cast<const float*>(smem + SM_BIAS);

    // epilogue: each element written exactly once
    #pragma unroll
    for (int mt = 0; mt < 4; ++mt) {
        const int row = m0 + warp_m * 64 + mt * 16 + g;
        #pragma unroll
        for (int nt = 0; nt < 8; ++nt) {
            const int lc  = warp_n * 64 + nt * 8 + tg * 2;
            const float b0 = biasp[lc], b1 = biasp[lc + 1];
            const size_t o0 = ((size_t)ib * BATCHN + row) * DDIM + n0 + lc;
            const size_t o1 = o0 + (size_t)8 * DDIM;
            *reinterpret_cast<float2*>(Y + o0) =
                make_float2(acc[mt][nt][0] + b0, acc[mt][nt][1] + b1);
            *reinterpret_cast<float2*>(Y + o1) =
                make_float2(acc[mt][nt][2] + b0, acc[mt][nt][3] + b1);
        }
    }
}

} // namespace

extern "C" void kernel_launch(void* const* d_in, const int* in_sizes, int n_in,
                              void* d_out, int out_size) {
    const float* X     = (const float*)d_in[0];
    const float* W     = (const float*)d_in[1];
    const float* b     = (const float*)d_in[2];
    const int*   i_idx = (const int*)d_in[3];
    const int*   j_idx = (const int*)d_in[4];
    float*       Y     = (float*)d_out;

    cudaFuncSetAttribute(bs_mma_kernel,
                         cudaFuncAttributeMaxDynamicSharedMemorySize, SMEM_TOTAL);

    prep_kernel<<<PREP_BLOCKS, 256>>>(X, W);
    bs_mma_kernel<<<dim3(BATCHN / BM, DDIM / BN, NBLK), THREADS, SMEM_TOTAL>>>(
        b, i_idx, j_idx, Y);
}